// round 13
// baseline (speedup 1.0000x reference)
#include <cuda_runtime.h>
#include <cuda_bf16.h>
#include <cstdint>

// Problem constants (fixed by reference)
#define VOCAB        100000
#define EMB_DIM      128
#define HIDDEN       256
#define NUM_CLASSES  20
#define B_SIZE       4096
#define S_LEN        200

// Scratch for pooled vectors: 4096 * 128 floats = 2 MB (static device array)
__device__ float g_pooled[B_SIZE * EMB_DIM];

// ---------------------------------------------------------------------------
// Kernel 1: embedding gather + masked mean pooling (R11 record variant,
// unchanged except the PDL trigger).  One block (128 threads = 4 warps) per
// sequence.  Token ids staged in smem; 6 outstanding LDG.128 per thread.
// ---------------------------------------------------------------------------
__global__ __launch_bounds__(128) void pool_kernel(
    const int* __restrict__ x,          // [B, S] token ids (int32)
    const int* __restrict__ seq_len,    // [B]
    const float* __restrict__ emb)      // [VOCAB, 128]
{
    cudaTriggerProgrammaticLaunchCompletion();

    __shared__ int    stok[S_LEN];
    __shared__ float4 red[4][32];

    const int b    = blockIdx.x;
    const int tid  = threadIdx.x;
    const int warp = tid >> 5;
    const int lane = tid & 31;

    const int L = seq_len[b];

    // stage token ids (coalesced, 2 passes of 128)
    {
        const int* xb = x + b * S_LEN;
        if (tid < S_LEN)       stok[tid]       = xb[tid];
        if (tid + 128 < S_LEN) stok[tid + 128] = xb[tid + 128];
    }
    __syncthreads();

    const float4* __restrict__ emb4 = reinterpret_cast<const float4*>(emb);

    float4 a0 = make_float4(0.f, 0.f, 0.f, 0.f);
    float4 a1 = make_float4(0.f, 0.f, 0.f, 0.f);
    float4 a2 = make_float4(0.f, 0.f, 0.f, 0.f);
    float4 a3 = make_float4(0.f, 0.f, 0.f, 0.f);
    float4 a4 = make_float4(0.f, 0.f, 0.f, 0.f);
    float4 a5 = make_float4(0.f, 0.f, 0.f, 0.f);

    int s = warp;
    for (; s + 20 < L; s += 24) {       // 6 independent gathers in flight
        int t0 = stok[s];
        int t1 = stok[s + 4];
        int t2 = stok[s + 8];
        int t3 = stok[s + 12];
        int t4 = stok[s + 16];
        int t5 = stok[s + 20];
        float4 v0 = __ldg(&emb4[(size_t)t0 * 32 + lane]);
        float4 v1 = __ldg(&emb4[(size_t)t1 * 32 + lane]);
        float4 v2 = __ldg(&emb4[(size_t)t2 * 32 + lane]);
        float4 v3 = __ldg(&emb4[(size_t)t3 * 32 + lane]);
        float4 v4 = __ldg(&emb4[(size_t)t4 * 32 + lane]);
        float4 v5 = __ldg(&emb4[(size_t)t5 * 32 + lane]);
        a0.x += v0.x; a0.y += v0.y; a0.z += v0.z; a0.w += v0.w;
        a1.x += v1.x; a1.y += v1.y; a1.z += v1.z; a1.w += v1.w;
        a2.x += v2.x; a2.y += v2.y; a2.z += v2.z; a2.w += v2.w;
        a3.x += v3.x; a3.y += v3.y; a3.z += v3.z; a3.w += v3.w;
        a4.x += v4.x; a4.y += v4.y; a4.z += v4.z; a4.w += v4.w;
        a5.x += v5.x; a5.y += v5.y; a5.z += v5.z; a5.w += v5.w;
    }
    for (; s < L; s += 4) {
        int t = stok[s];
        float4 v = __ldg(&emb4[(size_t)t * 32 + lane]);
        a0.x += v.x; a0.y += v.y; a0.z += v.z; a0.w += v.w;
    }
    a0.x += a1.x; a0.y += a1.y; a0.z += a1.z; a0.w += a1.w;
    a2.x += a3.x; a2.y += a3.y; a2.z += a3.z; a2.w += a3.w;
    a4.x += a5.x; a4.y += a5.y; a4.z += a5.z; a4.w += a5.w;
    a0.x += a2.x; a0.y += a2.y; a0.z += a2.z; a0.w += a2.w;
    a0.x += a4.x; a0.y += a4.y; a0.z += a4.z; a0.w += a4.w;

    red[warp][lane] = a0;
    __syncthreads();

    if (warp == 0) {
        float4 r0 = red[0][lane];
        float4 r1 = red[1][lane];
        float4 r2 = red[2][lane];
        float4 r3 = red[3][lane];
        float inv = 1.0f / (float)L;
        float4 o;
        o.x = (r0.x + r1.x + r2.x + r3.x) * inv;
        o.y = (r0.y + r1.y + r2.y + r3.y) * inv;
        o.z = (r0.z + r1.z + r2.z + r3.z) * inv;
        o.w = (r0.w + r1.w + r2.w + r3.w) * inv;
        reinterpret_cast<float4*>(g_pooled)[b * 32 + lane] = o;
    }
}

// ---------------------------------------------------------------------------
// Kernel 2: MLP with PDL prologue.  16 rows/block, 256 threads (thread j
// owns hidden column j).  Before cudaGridDependencySynchronize() (i.e.
// overlapped with the pool kernel's tail): stage W2 (20 KB) into smem,
// prefetch the first W1 k-tile into registers, load b1.  After sync: stage
// pooled rows and run the proven k+=8 FMA loop.
// ---------------------------------------------------------------------------
#define MLP_ROWS 16

__global__ __launch_bounds__(256) void mlp_kernel(
    const float* __restrict__ W1,   // [128, 256] row-major
    const float* __restrict__ b1,   // [256]
    const float* __restrict__ W2,   // [256, 20]  row-major
    const float* __restrict__ b2,   // [20]
    float* __restrict__ out)        // [B, 20]
{
    __shared__ float sp[MLP_ROWS][EMB_DIM];      // pooled tile  (8 KB)
    __shared__ float sh[MLP_ROWS][HIDDEN];       // hidden tile (16 KB)
    __shared__ float sW2[HIDDEN * NUM_CLASSES];  // W2           (20 KB)

    const int tid = threadIdx.x;
    const int rb  = blockIdx.x * MLP_ROWS;
    const int j   = tid;

    // ======== dependency-free prologue (overlaps the pool kernel) =========
    // stage W2 into smem: 5120 floats = 1280 float4
    {
        const float4* src = reinterpret_cast<const float4*>(W2);
        float4* dst = reinterpret_cast<float4*>(sW2);
        #pragma unroll
        for (int i = 0; i < 5; i++)
            dst[tid + i * 256] = src[tid + i * 256];
    }
    const float bj = b1[j];
    // prefetch first W1 k-tile (k = 0..7) into registers
    float pw0 = W1[0 * HIDDEN + j];
    float pw1 = W1[1 * HIDDEN + j];
    float pw2 = W1[2 * HIDDEN + j];
    float pw3 = W1[3 * HIDDEN + j];
    float pw4 = W1[4 * HIDDEN + j];
    float pw5 = W1[5 * HIDDEN + j];
    float pw6 = W1[6 * HIDDEN + j];
    float pw7 = W1[7 * HIDDEN + j];

    // ======== wait for pool kernel's writes to g_pooled ====================
    cudaGridDependencySynchronize();

    // stage 16 pooled rows (float4, coalesced)
    {
        const float4* src = reinterpret_cast<const float4*>(g_pooled + rb * EMB_DIM);
        float4* dst = reinterpret_cast<float4*>(&sp[0][0]);
        #pragma unroll
        for (int i = 0; i < 2; i++)
            dst[tid + i * 256] = src[tid + i * 256];
    }
    __syncthreads();

    float h[MLP_ROWS];
    #pragma unroll
    for (int r = 0; r < MLP_ROWS; r++) h[r] = bj;

    // peeled first k-tile from prefetched registers
    #pragma unroll
    for (int r = 0; r < MLP_ROWS; r++) {
        float4 p0 = *reinterpret_cast<const float4*>(&sp[r][0]);
        float4 p1 = *reinterpret_cast<const float4*>(&sp[r][4]);
        h[r] = fmaf(p0.x, pw0, h[r]);
        h[r] = fmaf(p0.y, pw1, h[r]);
        h[r] = fmaf(p0.z, pw2, h[r]);
        h[r] = fmaf(p0.w, pw3, h[r]);
        h[r] = fmaf(p1.x, pw4, h[r]);
        h[r] = fmaf(p1.y, pw5, h[r]);
        h[r] = fmaf(p1.z, pw6, h[r]);
        h[r] = fmaf(p1.w, pw7, h[r]);
    }

    #pragma unroll 1
    for (int k = 8; k < EMB_DIM; k += 8) {
        float w0 = W1[(k + 0) * HIDDEN + j];
        float w1 = W1[(k + 1) * HIDDEN + j];
        float w2 = W1[(k + 2) * HIDDEN + j];
        float w3 = W1[(k + 3) * HIDDEN + j];
        float w4 = W1[(k + 4) * HIDDEN + j];
        float w5 = W1[(k + 5) * HIDDEN + j];
        float w6 = W1[(k + 6) * HIDDEN + j];
        float w7 = W1[(k + 7) * HIDDEN + j];
        #pragma unroll
        for (int r = 0; r < MLP_ROWS; r++) {
            float4 p0 = *reinterpret_cast<const float4*>(&sp[r][k]);      // smem bcast
            float4 p1 = *reinterpret_cast<const float4*>(&sp[r][k + 4]);
            h[r] = fmaf(p0.x, w0, h[r]);
            h[r] = fmaf(p0.y, w1, h[r]);
            h[r] = fmaf(p0.z, w2, h[r]);
            h[r] = fmaf(p0.w, w3, h[r]);
            h[r] = fmaf(p1.x, w4, h[r]);
            h[r] = fmaf(p1.y, w5, h[r]);
            h[r] = fmaf(p1.z, w6, h[r]);
            h[r] = fmaf(p1.w, w7, h[r]);
        }
    }
    #pragma unroll
    for (int r = 0; r < MLP_ROWS; r++)
        sh[r][j] = fmaxf(h[r], 0.0f);
    __syncthreads();

    // output layer: 16 rows x 20 classes = 320 dots of length 256 (W2 in smem)
    for (int o = tid; o < MLP_ROWS * NUM_CLASSES; o += 256) {
        int r = o / NUM_CLASSES;
        int c = o % NUM_CLASSES;
        float acc = b2[c];
        #pragma unroll 8
        for (int k = 0; k < HIDDEN; k++)
            acc = fmaf(sh[r][k], sW2[k * NUM_CLASSES + c], acc);
        out[(rb + r) * NUM_CLASSES + c] = acc;
    }
}

// ---------------------------------------------------------------------------
// Launch: pool, then mlp as a programmatic dependent launch so mlp's
// prologue overlaps pool's tail; griddepsync provides correctness.
// ---------------------------------------------------------------------------
extern "C" void kernel_launch(void* const* d_in, const int* in_sizes, int n_in,
                              void* d_out, int out_size)
{
    const int*   x   = (const int*)  d_in[0];
    const int*   len = (const int*)  d_in[1];
    const float* emb = (const float*)d_in[2];
    const float* W1  = (const float*)d_in[3];
    const float* b1  = (const float*)d_in[4];
    const float* W2  = (const float*)d_in[5];
    const float* b2  = (const float*)d_in[6];
    float* out = (float*)d_out;

    pool_kernel<<<B_SIZE, 128>>>(x, len, emb);

    cudaLaunchConfig_t cfg = {};
    cfg.gridDim  = dim3(B_SIZE / MLP_ROWS, 1, 1);
    cfg.blockDim = dim3(256, 1, 1);
    cfg.dynamicSmemBytes = 0;
    cfg.stream = 0;
    cudaLaunchAttribute attr[1];
    attr[0].id = cudaLaunchAttributeProgrammaticStreamSerialization;
    attr[0].val.programmaticStreamSerializationAllowed = 1;
    cfg.attrs = attr;
    cfg.numAttrs = 1;
    cudaLaunchKernelEx(&cfg, mlp_kernel, W1, b1, W2, b2, out);
}

// round 16
// speedup vs baseline: 1.3948x; 1.3948x over previous
#include <cuda_runtime.h>
#include <cuda_bf16.h>
#include <cstdint>

// Problem constants (fixed by reference)
#define VOCAB        100000
#define EMB_DIM      128
#define HIDDEN       256
#define NUM_CLASSES  20
#define B_SIZE       4096
#define S_LEN        200

// Scratch for pooled vectors: 4096 * 128 floats = 2 MB (static device array)
__device__ float g_pooled[B_SIZE * EMB_DIM];

// ---------------------------------------------------------------------------
// Kernel 1: embedding gather + masked mean pooling (R11 record variant).
// One block (128 threads = 4 warps) per sequence.  Token ids staged in smem;
// 6 outstanding LDG.128 per thread.
// ---------------------------------------------------------------------------
__global__ __launch_bounds__(128) void pool_kernel(
    const int* __restrict__ x,          // [B, S] token ids (int32)
    const int* __restrict__ seq_len,    // [B]
    const float* __restrict__ emb)      // [VOCAB, 128]
{
    __shared__ int    stok[S_LEN];
    __shared__ float4 red[4][32];

    const int b    = blockIdx.x;
    const int tid  = threadIdx.x;
    const int warp = tid >> 5;
    const int lane = tid & 31;

    const int L = seq_len[b];

    // stage token ids (coalesced, 2 passes of 128)
    {
        const int* xb = x + b * S_LEN;
        if (tid < S_LEN)       stok[tid]       = xb[tid];
        if (tid + 128 < S_LEN) stok[tid + 128] = xb[tid + 128];
    }
    __syncthreads();

    const float4* __restrict__ emb4 = reinterpret_cast<const float4*>(emb);

    float4 a0 = make_float4(0.f, 0.f, 0.f, 0.f);
    float4 a1 = make_float4(0.f, 0.f, 0.f, 0.f);
    float4 a2 = make_float4(0.f, 0.f, 0.f, 0.f);
    float4 a3 = make_float4(0.f, 0.f, 0.f, 0.f);
    float4 a4 = make_float4(0.f, 0.f, 0.f, 0.f);
    float4 a5 = make_float4(0.f, 0.f, 0.f, 0.f);

    int s = warp;
    for (; s + 20 < L; s += 24) {       // 6 independent gathers in flight
        int t0 = stok[s];
        int t1 = stok[s + 4];
        int t2 = stok[s + 8];
        int t3 = stok[s + 12];
        int t4 = stok[s + 16];
        int t5 = stok[s + 20];
        float4 v0 = __ldg(&emb4[(size_t)t0 * 32 + lane]);
        float4 v1 = __ldg(&emb4[(size_t)t1 * 32 + lane]);
        float4 v2 = __ldg(&emb4[(size_t)t2 * 32 + lane]);
        float4 v3 = __ldg(&emb4[(size_t)t3 * 32 + lane]);
        float4 v4 = __ldg(&emb4[(size_t)t4 * 32 + lane]);
        float4 v5 = __ldg(&emb4[(size_t)t5 * 32 + lane]);
        a0.x += v0.x; a0.y += v0.y; a0.z += v0.z; a0.w += v0.w;
        a1.x += v1.x; a1.y += v1.y; a1.z += v1.z; a1.w += v1.w;
        a2.x += v2.x; a2.y += v2.y; a2.z += v2.z; a2.w += v2.w;
        a3.x += v3.x; a3.y += v3.y; a3.z += v3.z; a3.w += v3.w;
        a4.x += v4.x; a4.y += v4.y; a4.z += v4.z; a4.w += v4.w;
        a5.x += v5.x; a5.y += v5.y; a5.z += v5.z; a5.w += v5.w;
    }
    for (; s < L; s += 4) {
        int t = stok[s];
        float4 v = __ldg(&emb4[(size_t)t * 32 + lane]);
        a0.x += v.x; a0.y += v.y; a0.z += v.z; a0.w += v.w;
    }
    a0.x += a1.x; a0.y += a1.y; a0.z += a1.z; a0.w += a1.w;
    a2.x += a3.x; a2.y += a3.y; a2.z += a3.z; a2.w += a3.w;
    a4.x += a5.x; a4.y += a5.y; a4.z += a5.z; a4.w += a5.w;
    a0.x += a2.x; a0.y += a2.y; a0.z += a2.z; a0.w += a2.w;
    a0.x += a4.x; a0.y += a4.y; a0.z += a4.z; a0.w += a4.w;

    red[warp][lane] = a0;
    __syncthreads();

    if (warp == 0) {
        float4 r0 = red[0][lane];
        float4 r1 = red[1][lane];
        float4 r2 = red[2][lane];
        float4 r3 = red[3][lane];
        float inv = 1.0f / (float)L;
        float4 o;
        o.x = (r0.x + r1.x + r2.x + r3.x) * inv;
        o.y = (r0.y + r1.y + r2.y + r3.y) * inv;
        o.z = (r0.z + r1.z + r2.z + r3.z) * inv;
        o.w = (r0.w + r1.w + r2.w + r3.w) * inv;
        reinterpret_cast<float4*>(g_pooled)[b * 32 + lane] = o;
    }
}

// ---------------------------------------------------------------------------
// Kernel 2: MLP (plain launch).  16 rows/block, 256 threads (thread j owns
// hidden column j).  Prologue (independent of g_pooled): stage W2 into smem,
// prefetch W1 k-tile 0 into registers, load b1 — these overlap the pooled-row
// load latency.  Then the proven k+=8 FMA loop; layer 2 reads W2 from smem.
// ---------------------------------------------------------------------------
#define MLP_ROWS 16

__global__ __launch_bounds__(256) void mlp_kernel(
    const float* __restrict__ W1,   // [128, 256] row-major
    const float* __restrict__ b1,   // [256]
    const float* __restrict__ W2,   // [256, 20]  row-major
    const float* __restrict__ b2,   // [20]
    float* __restrict__ out)        // [B, 20]
{
    __shared__ float sp[MLP_ROWS][EMB_DIM];      // pooled tile  (8 KB)
    __shared__ float sh[MLP_ROWS][HIDDEN];       // hidden tile (16 KB)
    __shared__ float sW2[HIDDEN * NUM_CLASSES];  // W2           (20 KB)

    const int tid = threadIdx.x;
    const int rb  = blockIdx.x * MLP_ROWS;
    const int j   = tid;

    // ---- prologue: W2 -> smem, W1 tile 0 -> regs, biases ----
    {
        const float4* src = reinterpret_cast<const float4*>(W2);
        float4* dst = reinterpret_cast<float4*>(sW2);
        #pragma unroll
        for (int i = 0; i < 5; i++)
            dst[tid + i * 256] = src[tid + i * 256];
    }
    const float bj = b1[j];
    float pw0 = W1[0 * HIDDEN + j];
    float pw1 = W1[1 * HIDDEN + j];
    float pw2 = W1[2 * HIDDEN + j];
    float pw3 = W1[3 * HIDDEN + j];
    float pw4 = W1[4 * HIDDEN + j];
    float pw5 = W1[5 * HIDDEN + j];
    float pw6 = W1[6 * HIDDEN + j];
    float pw7 = W1[7 * HIDDEN + j];

    // ---- stage 16 pooled rows (float4, coalesced) ----
    {
        const float4* src = reinterpret_cast<const float4*>(g_pooled + rb * EMB_DIM);
        float4* dst = reinterpret_cast<float4*>(&sp[0][0]);
        #pragma unroll
        for (int i = 0; i < 2; i++)
            dst[tid + i * 256] = src[tid + i * 256];
    }
    __syncthreads();

    float h[MLP_ROWS];
    #pragma unroll
    for (int r = 0; r < MLP_ROWS; r++) h[r] = bj;

    // peeled first k-tile from prefetched registers
    #pragma unroll
    for (int r = 0; r < MLP_ROWS; r++) {
        float4 p0 = *reinterpret_cast<const float4*>(&sp[r][0]);
        float4 p1 = *reinterpret_cast<const float4*>(&sp[r][4]);
        h[r] = fmaf(p0.x, pw0, h[r]);
        h[r] = fmaf(p0.y, pw1, h[r]);
        h[r] = fmaf(p0.z, pw2, h[r]);
        h[r] = fmaf(p0.w, pw3, h[r]);
        h[r] = fmaf(p1.x, pw4, h[r]);
        h[r] = fmaf(p1.y, pw5, h[r]);
        h[r] = fmaf(p1.z, pw6, h[r]);
        h[r] = fmaf(p1.w, pw7, h[r]);
    }

    #pragma unroll 1
    for (int k = 8; k < EMB_DIM; k += 8) {
        float w0 = W1[(k + 0) * HIDDEN + j];
        float w1 = W1[(k + 1) * HIDDEN + j];
        float w2 = W1[(k + 2) * HIDDEN + j];
        float w3 = W1[(k + 3) * HIDDEN + j];
        float w4 = W1[(k + 4) * HIDDEN + j];
        float w5 = W1[(k + 5) * HIDDEN + j];
        float w6 = W1[(k + 6) * HIDDEN + j];
        float w7 = W1[(k + 7) * HIDDEN + j];
        #pragma unroll
        for (int r = 0; r < MLP_ROWS; r++) {
            float4 p0 = *reinterpret_cast<const float4*>(&sp[r][k]);      // smem bcast
            float4 p1 = *reinterpret_cast<const float4*>(&sp[r][k + 4]);
            h[r] = fmaf(p0.x, w0, h[r]);
            h[r] = fmaf(p0.y, w1, h[r]);
            h[r] = fmaf(p0.z, w2, h[r]);
            h[r] = fmaf(p0.w, w3, h[r]);
            h[r] = fmaf(p1.x, w4, h[r]);
            h[r] = fmaf(p1.y, w5, h[r]);
            h[r] = fmaf(p1.z, w6, h[r]);
            h[r] = fmaf(p1.w, w7, h[r]);
        }
    }
    #pragma unroll
    for (int r = 0; r < MLP_ROWS; r++)
        sh[r][j] = fmaxf(h[r], 0.0f);
    __syncthreads();

    // output layer: 16 rows x 20 classes = 320 dots of length 256 (W2 in smem)
    for (int o = tid; o < MLP_ROWS * NUM_CLASSES; o += 256) {
        int r = o / NUM_CLASSES;
        int c = o % NUM_CLASSES;
        float acc = b2[c];
        #pragma unroll 8
        for (int k = 0; k < HIDDEN; k++)
            acc = fmaf(sh[r][k], sW2[k * NUM_CLASSES + c], acc);
        out[(rb + r) * NUM_CLASSES + c] = acc;
    }
}

// ---------------------------------------------------------------------------
// Inputs (metadata order): x[int32 B*S], seq_lengths[int32 B], emb[f32],
//                          W1[f32], b1[f32], W2[f32], b2[f32]
// Output: f32 [B, 20]
// ---------------------------------------------------------------------------
extern "C" void kernel_launch(void* const* d_in, const int* in_sizes, int n_in,
                              void* d_out, int out_size)
{
    const int*   x   = (const int*)  d_in[0];
    const int*   len = (const int*)  d_in[1];
    const float* emb = (const float*)d_in[2];
    const float* W1  = (const float*)d_in[3];
    const float* b1  = (const float*)d_in[4];
    const float* W2  = (const float*)d_in[5];
    const float* b2  = (const float*)d_in[6];
    float* out = (float*)d_out;

    pool_kernel<<<B_SIZE, 128>>>(x, len, emb);
    mlp_kernel<<<B_SIZE / MLP_ROWS, 256>>>(W1, b1, W2, b2, out);
}